// round 15
// baseline (speedup 1.0000x reference)
#include <cuda_runtime.h>

#define NT 100000
#define NC 100000
#define NE 1600000
#define NP 200000
#define HD 128

// ---- scratch (static __device__, zero at load; u kernels restore zeros) ----
__device__ float  g_dis_t[NT];     // raw truck degree
__device__ float  g_sum_t[NT];     // unscaled truck sum
__device__ float4 g_gc4[NC];       // unscaled car sum
__device__ float4 g_xd4[NC];       // (x0,x1,x2, raw weighted degree)
__device__ float4 g_u[NT + NC];    // per-node compact coefficients

__device__ __forceinline__ void red_add_v4(float4* addr, float a, float b, float c, float d) {
    asm volatile("red.global.add.v4.f32 [%0], {%1,%2,%3,%4};"
                 :: "l"(addr), "f"(a), "f"(b), "f"(c), "f"(d) : "memory");
}

// ================= stream A: truck chain (+ xcar packing) =================
__global__ void __launch_bounds__(256, 8) k_deg_t(const int* __restrict__ eit,
                                                  const float* __restrict__ xcar) {
    int t = blockIdx.x * blockDim.x + threadIdx.x;
    int i = t * 4;
    if (i < NC) {
        float4 x0 = __ldcs((const float4*)(xcar + 3 * i));
        float4 x1 = __ldcs((const float4*)(xcar + 3 * i + 4));
        float4 x2 = __ldcs((const float4*)(xcar + 3 * i + 8));
        float* p0 = (float*)&g_xd4[i + 0];
        float* p1 = (float*)&g_xd4[i + 1];
        float* p2 = (float*)&g_xd4[i + 2];
        float* p3 = (float*)&g_xd4[i + 3];
        p0[0] = x0.x; p0[1] = x0.y; p0[2] = x0.z;
        p1[0] = x0.w; p1[1] = x1.x; p1[2] = x1.y;
        p2[0] = x1.z; p2[1] = x1.w; p2[2] = x2.x;
        p3[0] = x2.y; p3[1] = x2.z; p3[2] = x2.w;
    }
    int base = t * 8;
    if (base >= NE) return;
    int4 a = __ldcs((const int4*)(eit + NE + base));
    int4 b = __ldcs((const int4*)(eit + NE + base + 4));
    atomicAdd(&g_dis_t[a.x], 1.0f);
    atomicAdd(&g_dis_t[a.y], 1.0f);
    atomicAdd(&g_dis_t[a.z], 1.0f);
    atomicAdd(&g_dis_t[a.w], 1.0f);
    atomicAdd(&g_dis_t[b.x], 1.0f);
    atomicAdd(&g_dis_t[b.y], 1.0f);
    atomicAdd(&g_dis_t[b.z], 1.0f);
    atomicAdd(&g_dis_t[b.w], 1.0f);
}

__global__ void __launch_bounds__(256, 6) k_agg_t(const int* __restrict__ eit) {
    int t = blockIdx.x * blockDim.x + threadIdx.x;
    int base = t * 4;
    if (base >= NE) return;
    int4 rt4 = __ldcs((const int4*)(eit + base));
    int4 ct4 = __ldcs((const int4*)(eit + NE + base));
    int rt[4] = {rt4.x, rt4.y, rt4.z, rt4.w};
    int ct[4] = {ct4.x, ct4.y, ct4.z, ct4.w};
    float dtr[4];
    #pragma unroll
    for (int k = 0; k < 4; k++) dtr[k] = g_dis_t[rt[k]];
    #pragma unroll
    for (int k = 0; k < 4; k++)
        atomicAdd(&g_sum_t[ct[k]], rsqrtf(dtr[k] + 1.0f));
}

// 4 nodes/thread, vector loads/stores on flat arrays
__global__ void __launch_bounds__(256) k_u_t() {
    int t = blockIdx.x * blockDim.x + threadIdx.x;
    int n = t * 4;
    if (n >= NT) return;
    float4 dg = *(float4*)&g_dis_t[n];
    float4 sm = *(float4*)&g_sum_t[n];
    float d0 = rsqrtf(dg.x + 1.0f), d1 = rsqrtf(dg.y + 1.0f);
    float d2 = rsqrtf(dg.z + 1.0f), d3 = rsqrtf(dg.w + 1.0f);
    g_u[n + 0] = make_float4(d0 * sm.x + d0 * d0, 1.f, 0.f, 0.f);
    g_u[n + 1] = make_float4(d1 * sm.y + d1 * d1, 1.f, 0.f, 0.f);
    g_u[n + 2] = make_float4(d2 * sm.z + d2 * d2, 1.f, 0.f, 0.f);
    g_u[n + 3] = make_float4(d3 * sm.w + d3 * d3, 1.f, 0.f, 0.f);
    *(float4*)&g_dis_t[n] = make_float4(0.f, 0.f, 0.f, 0.f);
    *(float4*)&g_sum_t[n] = make_float4(0.f, 0.f, 0.f, 0.f);
}

// ================= stream B: car chain =================
__global__ void __launch_bounds__(256, 8) k_deg_c(const int* __restrict__ eic,
                                                  const float* __restrict__ ew) {
    int t = blockIdx.x * blockDim.x + threadIdx.x;
    int base = t * 8;
    if (base >= NE) return;
    int4   ca = __ldcs((const int4*)(eic + NE + base));
    int4   cb = __ldcs((const int4*)(eic + NE + base + 4));
    float4 wa = __ldcs((const float4*)(ew + base));
    float4 wb = __ldcs((const float4*)(ew + base + 4));
    atomicAdd(&g_xd4[ca.x].w, wa.x);
    atomicAdd(&g_xd4[ca.y].w, wa.y);
    atomicAdd(&g_xd4[ca.z].w, wa.z);
    atomicAdd(&g_xd4[ca.w].w, wa.w);
    atomicAdd(&g_xd4[cb.x].w, wb.x);
    atomicAdd(&g_xd4[cb.y].w, wb.y);
    atomicAdd(&g_xd4[cb.z].w, wb.z);
    atomicAdd(&g_xd4[cb.w].w, wb.w);
}

__global__ void __launch_bounds__(256, 6) k_agg_c(const int* __restrict__ eic,
                                                  const float* __restrict__ ew) {
    int t = blockIdx.x * blockDim.x + threadIdx.x;
    int base = t * 4;
    if (base >= NE) return;
    int4   rc4 = __ldcs((const int4*)(eic + base));
    int4   cc4 = __ldcs((const int4*)(eic + NE + base));
    float4 w4  = __ldcs((const float4*)(ew + base));
    int rc[4] = {rc4.x, rc4.y, rc4.z, rc4.w};
    int cc[4] = {cc4.x, cc4.y, cc4.z, cc4.w};
    float w[4] = {w4.x, w4.y, w4.z, w4.w};
    float4 xd[4];
    #pragma unroll
    for (int k = 0; k < 4; k++) xd[k] = g_xd4[rc[k]];
    #pragma unroll
    for (int k = 0; k < 4; k++) {
        float nw = rsqrtf(xd[k].w + 1.0f) * w[k];
        red_add_v4(&g_gc4[cc[k]], nw * xd[k].x, nw * xd[k].y, nw * xd[k].z, 0.f);
    }
}

// 4 nodes/thread (loads already float4-natural)
__global__ void __launch_bounds__(256) k_u_c() {
    int t = blockIdx.x * blockDim.x + threadIdx.x;
    int c = t * 4;
    if (c >= NC) return;
    #pragma unroll
    for (int k = 0; k < 4; k++) {
        float4 gc = g_gc4[c + k];
        float4 xd = g_xd4[c + k];
        float d  = rsqrtf(xd.w + 1.0f);
        float dd = d * d;
        g_u[NT + c + k] = make_float4(d * gc.x + dd * xd.x,
                                      d * gc.y + dd * xd.y,
                                      d * gc.z + dd * xd.z,
                                      1.f);
        g_gc4[c + k] = make_float4(0.f, 0.f, 0.f, 0.f);
        ((float*)&g_xd4[c + k])[3] = 0.f;
    }
}

// ================= pair scoring: 2 pairs/thread (R13 champion form) =================
__global__ void __launch_bounds__(256) k_pair(const int* __restrict__ src,
                                              const int* __restrict__ dst,
                                              const float* __restrict__ Wt,
                                              const float* __restrict__ bt,
                                              const float* __restrict__ Wc,
                                              const float* __restrict__ bc,
                                              const float* __restrict__ wl,
                                              const float* __restrict__ bl,
                                              float* __restrict__ out) {
    __shared__ float B[6][HD];
    __shared__ float Bw[HD];
    __shared__ float M[36];
    {
        int h = threadIdx.x;
        if (h < HD) {
            B[0][h] = __ldg(Wt + h);
            B[1][h] = __ldg(bt + h);
            B[2][h] = __ldg(Wc + h);
            B[3][h] = __ldg(Wc + HD + h);
            B[4][h] = __ldg(Wc + 2 * HD + h);
            B[5][h] = __ldg(bc + h);
            Bw[h]   = __ldg(wl + h);
        }
        __syncthreads();
        int warp = threadIdx.x >> 5, lane = threadIdx.x & 31;
        for (int pi = warp; pi < 36; pi += 8) {
            int i = pi / 6, j = pi % 6;
            float s = 0.f;
            #pragma unroll
            for (int tt = lane; tt < HD; tt += 32)
                s += B[i][tt] * B[j][tt] * Bw[tt];
            #pragma unroll
            for (int o = 16; o > 0; o >>= 1)
                s += __shfl_xor_sync(0xffffffff, s, o);
            if (lane == 0) M[pi] = s;
        }
        __syncthreads();
    }

    int t = blockIdx.x * blockDim.x + threadIdx.x;
    int base = t * 2;
    if (base >= NP) return;
    int2 s2 = __ldcs((const int2*)(src + base));
    int2 d2 = __ldcs((const int2*)(dst + base));
    float blv = __ldg(bl);
    int ss[2] = {s2.x, s2.y};
    int dd[2] = {d2.x, d2.y};
    float4 usv[2], udv[2];
    #pragma unroll
    for (int k = 0; k < 2; k++) { usv[k] = g_u[ss[k]]; udv[k] = g_u[dd[k]]; }
    float res[2];
    #pragma unroll
    for (int k = 0; k < 2; k++) {
        float us[6] = {0.f, 0.f, 0.f, 0.f, 0.f, 0.f};
        float ud[6] = {0.f, 0.f, 0.f, 0.f, 0.f, 0.f};
        if (ss[k] < NT) { us[0] = usv[k].x; us[1] = usv[k].y; }
        else            { us[2] = usv[k].x; us[3] = usv[k].y; us[4] = usv[k].z; us[5] = usv[k].w; }
        if (dd[k] < NT) { ud[0] = udv[k].x; ud[1] = udv[k].y; }
        else            { ud[2] = udv[k].x; ud[3] = udv[k].y; ud[4] = udv[k].z; ud[5] = udv[k].w; }
        float acc = blv;
        #pragma unroll
        for (int i = 0; i < 6; i++) {
            float tt = 0.f;
            #pragma unroll
            for (int j = 0; j < 6; j++)
                tt += M[6 * i + j] * ud[j];
            acc += us[i] * tt;
        }
        res[k] = acc;
    }
    out[base] = res[0];
    out[base + 1] = res[1];
}

extern "C" void kernel_launch(void* const* d_in, const int* in_sizes, int n_in,
                              void* d_out, int out_size) {
    const float* xcar = (const float*)d_in[0];
    const int*   eit  = (const int*)d_in[1];
    const int*   eic  = (const int*)d_in[2];
    const float* ew   = (const float*)d_in[3];
    const int*   src  = (const int*)d_in[4];
    const int*   dst  = (const int*)d_in[5];
    int w0 = (in_sizes[6] == 1) ? 7 : 6;
    const float* Wt = (const float*)d_in[w0 + 0];
    const float* bt = (const float*)d_in[w0 + 1];
    const float* Wc = (const float*)d_in[w0 + 2];
    const float* bc = (const float*)d_in[w0 + 3];
    const float* wl = (const float*)d_in[w0 + 4];
    const float* bl = (const float*)d_in[w0 + 5];
    float* out = (float*)d_out;

    static cudaStream_t sB = 0;
    static cudaEvent_t eFork = 0, eDegT = 0, eUc = 0;
    if (sB == 0) {
        cudaStreamCreateWithFlags(&sB, cudaStreamNonBlocking);
        cudaEventCreateWithFlags(&eFork, cudaEventDisableTiming);
        cudaEventCreateWithFlags(&eDegT, cudaEventDisableTiming);
        cudaEventCreateWithFlags(&eUc,   cudaEventDisableTiming);
    }

    const int TPB = 256;
    const int GE8 = (NE / 8 + TPB - 1) / TPB;
    const int GE4 = (NE / 4 + TPB - 1) / TPB;

    cudaEventRecord(eFork, 0);
    cudaStreamWaitEvent(sB, eFork, 0);

    // stream A: truck chain (deg_t also packs xcar into xd4.xyz)
    k_deg_t<<<GE8, TPB>>>(eit, xcar);
    cudaEventRecord(eDegT, 0);
    k_agg_t<<<GE4, TPB>>>(eit);
    k_u_t<<<(NT / 4 + TPB - 1) / TPB, TPB>>>();

    // stream B: car chain (agg_c needs xd4.xyz packed by deg_t)
    k_deg_c<<<GE8, TPB, 0, sB>>>(eic, ew);
    cudaStreamWaitEvent(sB, eDegT, 0);
    k_agg_c<<<GE4, TPB, 0, sB>>>(eic, ew);
    k_u_c<<<(NC / 4 + TPB - 1) / TPB, TPB, 0, sB>>>();
    cudaEventRecord(eUc, sB);

    // join + score on stream A
    cudaStreamWaitEvent(0, eUc, 0);
    k_pair<<<(NP / 2 + TPB - 1) / TPB, TPB>>>(src, dst, Wt, bt, Wc, bc, wl, bl, out);
}

// round 16
// speedup vs baseline: 1.0808x; 1.0808x over previous
#include <cuda_runtime.h>

#define NT 100000
#define NC 100000
#define NE 1600000
#define NP 200000
#define HD 128

// ---- scratch (static __device__, zero at load; u kernels restore zeros) ----
__device__ float  g_dis_t[NT];     // raw truck degree
__device__ float  g_sum_t[NT];     // unscaled truck sum
__device__ float4 g_gc4[NC];       // unscaled car sum
__device__ float4 g_xd4[NC];       // (x0,x1,x2, raw weighted degree)
__device__ float4 g_u[NT + NC];    // per-node compact coefficients

__device__ __forceinline__ void red_add_v4(float4* addr, float a, float b, float c, float d) {
    asm volatile("red.global.add.v4.f32 [%0], {%1,%2,%3,%4};"
                 :: "l"(addr), "f"(a), "f"(b), "f"(c), "f"(d) : "memory");
}

// ================= stream A: truck chain (+ xcar packing) =================
// 8 edges/thread; also packs xcar into g_xd4.xyz (disjoint from car-deg atomics on .w)
__global__ void __launch_bounds__(256, 8) k_deg_t(const int* __restrict__ eit,
                                                  const float* __restrict__ xcar) {
    int t = blockIdx.x * blockDim.x + threadIdx.x;
    int i = t * 4;
    if (i < NC) {
        float4 x0 = __ldcs((const float4*)(xcar + 3 * i));
        float4 x1 = __ldcs((const float4*)(xcar + 3 * i + 4));
        float4 x2 = __ldcs((const float4*)(xcar + 3 * i + 8));
        float* p0 = (float*)&g_xd4[i + 0];
        float* p1 = (float*)&g_xd4[i + 1];
        float* p2 = (float*)&g_xd4[i + 2];
        float* p3 = (float*)&g_xd4[i + 3];
        p0[0] = x0.x; p0[1] = x0.y; p0[2] = x0.z;
        p1[0] = x0.w; p1[1] = x1.x; p1[2] = x1.y;
        p2[0] = x1.z; p2[1] = x1.w; p2[2] = x2.x;
        p3[0] = x2.y; p3[1] = x2.z; p3[2] = x2.w;
    }
    int base = t * 8;
    if (base >= NE) return;
    int4 a = __ldcs((const int4*)(eit + NE + base));
    int4 b = __ldcs((const int4*)(eit + NE + base + 4));
    atomicAdd(&g_dis_t[a.x], 1.0f);
    atomicAdd(&g_dis_t[a.y], 1.0f);
    atomicAdd(&g_dis_t[a.z], 1.0f);
    atomicAdd(&g_dis_t[a.w], 1.0f);
    atomicAdd(&g_dis_t[b.x], 1.0f);
    atomicAdd(&g_dis_t[b.y], 1.0f);
    atomicAdd(&g_dis_t[b.z], 1.0f);
    atomicAdd(&g_dis_t[b.w], 1.0f);
}

__global__ void __launch_bounds__(256, 6) k_agg_t(const int* __restrict__ eit) {
    int t = blockIdx.x * blockDim.x + threadIdx.x;
    int base = t * 4;
    if (base >= NE) return;
    int4 rt4 = __ldcs((const int4*)(eit + base));
    int4 ct4 = __ldcs((const int4*)(eit + NE + base));
    int rt[4] = {rt4.x, rt4.y, rt4.z, rt4.w};
    int ct[4] = {ct4.x, ct4.y, ct4.z, ct4.w};
    float dtr[4];
    #pragma unroll
    for (int k = 0; k < 4; k++) dtr[k] = g_dis_t[rt[k]];
    #pragma unroll
    for (int k = 0; k < 4; k++)
        atomicAdd(&g_sum_t[ct[k]], rsqrtf(dtr[k] + 1.0f));
}

// 1 node/thread — wide grid hides latency (R14/R15 showed 4/thread regresses)
__global__ void __launch_bounds__(256) k_u_t() {
    int n = blockIdx.x * blockDim.x + threadIdx.x;
    if (n >= NT) return;
    float d = rsqrtf(g_dis_t[n] + 1.0f);
    g_u[n] = make_float4(d * g_sum_t[n] + d * d, 1.f, 0.f, 0.f);
    g_dis_t[n] = 0.f;
    g_sum_t[n] = 0.f;
}

// ================= stream B: car chain =================
__global__ void __launch_bounds__(256, 8) k_deg_c(const int* __restrict__ eic,
                                                  const float* __restrict__ ew) {
    int t = blockIdx.x * blockDim.x + threadIdx.x;
    int base = t * 8;
    if (base >= NE) return;
    int4   ca = __ldcs((const int4*)(eic + NE + base));
    int4   cb = __ldcs((const int4*)(eic + NE + base + 4));
    float4 wa = __ldcs((const float4*)(ew + base));
    float4 wb = __ldcs((const float4*)(ew + base + 4));
    atomicAdd(&g_xd4[ca.x].w, wa.x);
    atomicAdd(&g_xd4[ca.y].w, wa.y);
    atomicAdd(&g_xd4[ca.z].w, wa.z);
    atomicAdd(&g_xd4[ca.w].w, wa.w);
    atomicAdd(&g_xd4[cb.x].w, wb.x);
    atomicAdd(&g_xd4[cb.y].w, wb.y);
    atomicAdd(&g_xd4[cb.z].w, wb.z);
    atomicAdd(&g_xd4[cb.w].w, wb.w);
}

__global__ void __launch_bounds__(256, 6) k_agg_c(const int* __restrict__ eic,
                                                  const float* __restrict__ ew) {
    int t = blockIdx.x * blockDim.x + threadIdx.x;
    int base = t * 4;
    if (base >= NE) return;
    int4   rc4 = __ldcs((const int4*)(eic + base));
    int4   cc4 = __ldcs((const int4*)(eic + NE + base));
    float4 w4  = __ldcs((const float4*)(ew + base));
    int rc[4] = {rc4.x, rc4.y, rc4.z, rc4.w};
    int cc[4] = {cc4.x, cc4.y, cc4.z, cc4.w};
    float w[4] = {w4.x, w4.y, w4.z, w4.w};
    float4 xd[4];
    #pragma unroll
    for (int k = 0; k < 4; k++) xd[k] = g_xd4[rc[k]];
    #pragma unroll
    for (int k = 0; k < 4; k++) {
        float nw = rsqrtf(xd[k].w + 1.0f) * w[k];
        red_add_v4(&g_gc4[cc[k]], nw * xd[k].x, nw * xd[k].y, nw * xd[k].z, 0.f);
    }
}

// 1 node/thread — wide grid
__global__ void __launch_bounds__(256) k_u_c() {
    int c = blockIdx.x * blockDim.x + threadIdx.x;
    if (c >= NC) return;
    float4 gc = g_gc4[c];
    float4 xd = g_xd4[c];
    float d  = rsqrtf(xd.w + 1.0f);
    float dd = d * d;
    g_u[NT + c] = make_float4(d * gc.x + dd * xd.x,
                              d * gc.y + dd * xd.y,
                              d * gc.z + dd * xd.z,
                              1.f);
    g_gc4[c] = make_float4(0.f, 0.f, 0.f, 0.f);
    ((float*)&g_xd4[c])[3] = 0.f;
}

// ================= pair scoring: 2 pairs/thread, in-block M compute =================
__global__ void __launch_bounds__(256) k_pair(const int* __restrict__ src,
                                              const int* __restrict__ dst,
                                              const float* __restrict__ Wt,
                                              const float* __restrict__ bt,
                                              const float* __restrict__ Wc,
                                              const float* __restrict__ bc,
                                              const float* __restrict__ wl,
                                              const float* __restrict__ bl,
                                              float* __restrict__ out) {
    __shared__ float B[6][HD];
    __shared__ float Bw[HD];
    __shared__ float M[36];
    {
        int h = threadIdx.x;
        if (h < HD) {
            B[0][h] = __ldg(Wt + h);
            B[1][h] = __ldg(bt + h);
            B[2][h] = __ldg(Wc + h);
            B[3][h] = __ldg(Wc + HD + h);
            B[4][h] = __ldg(Wc + 2 * HD + h);
            B[5][h] = __ldg(bc + h);
            Bw[h]   = __ldg(wl + h);
        }
        __syncthreads();
        int warp = threadIdx.x >> 5, lane = threadIdx.x & 31;
        for (int pi = warp; pi < 36; pi += 8) {
            int i = pi / 6, j = pi % 6;
            float s = 0.f;
            #pragma unroll
            for (int tt = lane; tt < HD; tt += 32)
                s += B[i][tt] * B[j][tt] * Bw[tt];
            #pragma unroll
            for (int o = 16; o > 0; o >>= 1)
                s += __shfl_xor_sync(0xffffffff, s, o);
            if (lane == 0) M[pi] = s;
        }
        __syncthreads();
    }

    int t = blockIdx.x * blockDim.x + threadIdx.x;
    int base = t * 2;
    if (base >= NP) return;
    int2 s2 = __ldcs((const int2*)(src + base));
    int2 d2 = __ldcs((const int2*)(dst + base));
    float blv = __ldg(bl);
    int ss[2] = {s2.x, s2.y};
    int dd[2] = {d2.x, d2.y};
    float4 usv[2], udv[2];
    #pragma unroll
    for (int k = 0; k < 2; k++) { usv[k] = g_u[ss[k]]; udv[k] = g_u[dd[k]]; }
    float res[2];
    #pragma unroll
    for (int k = 0; k < 2; k++) {
        float us[6] = {0.f, 0.f, 0.f, 0.f, 0.f, 0.f};
        float ud[6] = {0.f, 0.f, 0.f, 0.f, 0.f, 0.f};
        if (ss[k] < NT) { us[0] = usv[k].x; us[1] = usv[k].y; }
        else            { us[2] = usv[k].x; us[3] = usv[k].y; us[4] = usv[k].z; us[5] = usv[k].w; }
        if (dd[k] < NT) { ud[0] = udv[k].x; ud[1] = udv[k].y; }
        else            { ud[2] = udv[k].x; ud[3] = udv[k].y; ud[4] = udv[k].z; ud[5] = udv[k].w; }
        float acc = blv;
        #pragma unroll
        for (int i = 0; i < 6; i++) {
            float tt = 0.f;
            #pragma unroll
            for (int j = 0; j < 6; j++)
                tt += M[6 * i + j] * ud[j];
            acc += us[i] * tt;
        }
        res[k] = acc;
    }
    out[base] = res[0];
    out[base + 1] = res[1];
}

extern "C" void kernel_launch(void* const* d_in, const int* in_sizes, int n_in,
                              void* d_out, int out_size) {
    const float* xcar = (const float*)d_in[0];
    const int*   eit  = (const int*)d_in[1];
    const int*   eic  = (const int*)d_in[2];
    const float* ew   = (const float*)d_in[3];
    const int*   src  = (const int*)d_in[4];
    const int*   dst  = (const int*)d_in[5];
    int w0 = (in_sizes[6] == 1) ? 7 : 6;
    const float* Wt = (const float*)d_in[w0 + 0];
    const float* bt = (const float*)d_in[w0 + 1];
    const float* Wc = (const float*)d_in[w0 + 2];
    const float* bc = (const float*)d_in[w0 + 3];
    const float* wl = (const float*)d_in[w0 + 4];
    const float* bl = (const float*)d_in[w0 + 5];
    float* out = (float*)d_out;

    static cudaStream_t sB = 0;
    static cudaEvent_t eFork = 0, eDegT = 0, eUc = 0;
    if (sB == 0) {
        cudaStreamCreateWithFlags(&sB, cudaStreamNonBlocking);
        cudaEventCreateWithFlags(&eFork, cudaEventDisableTiming);
        cudaEventCreateWithFlags(&eDegT, cudaEventDisableTiming);
        cudaEventCreateWithFlags(&eUc,   cudaEventDisableTiming);
    }

    const int TPB = 256;
    const int GE8 = (NE / 8 + TPB - 1) / TPB;
    const int GE4 = (NE / 4 + TPB - 1) / TPB;

    cudaEventRecord(eFork, 0);
    cudaStreamWaitEvent(sB, eFork, 0);

    // stream A: truck chain (deg_t also packs xcar into xd4.xyz)
    k_deg_t<<<GE8, TPB>>>(eit, xcar);
    cudaEventRecord(eDegT, 0);
    k_agg_t<<<GE4, TPB>>>(eit);
    k_u_t<<<(NT + TPB - 1) / TPB, TPB>>>();

    // stream B: car chain (agg_c needs xd4.xyz packed by deg_t)
    k_deg_c<<<GE8, TPB, 0, sB>>>(eic, ew);
    cudaStreamWaitEvent(sB, eDegT, 0);
    k_agg_c<<<GE4, TPB, 0, sB>>>(eic, ew);
    k_u_c<<<(NC + TPB - 1) / TPB, TPB, 0, sB>>>();
    cudaEventRecord(eUc, sB);

    // join + score on stream A
    cudaStreamWaitEvent(0, eUc, 0);
    k_pair<<<(NP / 2 + TPB - 1) / TPB, TPB>>>(src, dst, Wt, bt, Wc, bc, wl, bl, out);
}

// round 17
// speedup vs baseline: 1.0851x; 1.0040x over previous
#include <cuda_runtime.h>

#define NT 100000
#define NC 100000
#define NE 1600000
#define NP 200000
#define HD 128

// ---- scratch (static __device__, zero at load; u kernels restore zeros) ----
__device__ float  g_dis_t[NT];     // raw truck degree
__device__ float  g_sum_t[NT];     // unscaled truck sum
__device__ float4 g_gc4[NC];       // unscaled car sum
__device__ float4 g_xd4[NC];       // (x0,x1,x2, raw weighted degree)
__device__ float4 g_u[NT + NC];    // per-node compact coefficients

__device__ __forceinline__ void red_add_v4(float4* addr, float a, float b, float c, float d) {
    asm volatile("red.global.add.v4.f32 [%0], {%1,%2,%3,%4};"
                 :: "l"(addr), "f"(a), "f"(b), "f"(c), "f"(d) : "memory");
}

// ================= stream A: truck chain (+ xcar packing) =================
// 8 edges/thread; also packs xcar into g_xd4.xyz (disjoint from car-deg atomics on .w)
__global__ void __launch_bounds__(128, 16) k_deg_t(const int* __restrict__ eit,
                                                   const float* __restrict__ xcar) {
    int t = blockIdx.x * blockDim.x + threadIdx.x;
    int i = t * 4;
    if (i < NC) {
        float4 x0 = __ldcs((const float4*)(xcar + 3 * i));
        float4 x1 = __ldcs((const float4*)(xcar + 3 * i + 4));
        float4 x2 = __ldcs((const float4*)(xcar + 3 * i + 8));
        float* p0 = (float*)&g_xd4[i + 0];
        float* p1 = (float*)&g_xd4[i + 1];
        float* p2 = (float*)&g_xd4[i + 2];
        float* p3 = (float*)&g_xd4[i + 3];
        p0[0] = x0.x; p0[1] = x0.y; p0[2] = x0.z;
        p1[0] = x0.w; p1[1] = x1.x; p1[2] = x1.y;
        p2[0] = x1.z; p2[1] = x1.w; p2[2] = x2.x;
        p3[0] = x2.y; p3[1] = x2.z; p3[2] = x2.w;
    }
    int base = t * 8;
    if (base >= NE) return;
    int4 a = __ldcs((const int4*)(eit + NE + base));
    int4 b = __ldcs((const int4*)(eit + NE + base + 4));
    atomicAdd(&g_dis_t[a.x], 1.0f);
    atomicAdd(&g_dis_t[a.y], 1.0f);
    atomicAdd(&g_dis_t[a.z], 1.0f);
    atomicAdd(&g_dis_t[a.w], 1.0f);
    atomicAdd(&g_dis_t[b.x], 1.0f);
    atomicAdd(&g_dis_t[b.y], 1.0f);
    atomicAdd(&g_dis_t[b.z], 1.0f);
    atomicAdd(&g_dis_t[b.w], 1.0f);
}

__global__ void __launch_bounds__(128, 12) k_agg_t(const int* __restrict__ eit) {
    int t = blockIdx.x * blockDim.x + threadIdx.x;
    int base = t * 4;
    if (base >= NE) return;
    int4 rt4 = __ldcs((const int4*)(eit + base));
    int4 ct4 = __ldcs((const int4*)(eit + NE + base));
    int rt[4] = {rt4.x, rt4.y, rt4.z, rt4.w};
    int ct[4] = {ct4.x, ct4.y, ct4.z, ct4.w};
    float dtr[4];
    #pragma unroll
    for (int k = 0; k < 4; k++) dtr[k] = g_dis_t[rt[k]];
    #pragma unroll
    for (int k = 0; k < 4; k++)
        atomicAdd(&g_sum_t[ct[k]], rsqrtf(dtr[k] + 1.0f));
}

// 1 node/thread — wide grid hides latency
__global__ void __launch_bounds__(256) k_u_t() {
    int n = blockIdx.x * blockDim.x + threadIdx.x;
    if (n >= NT) return;
    float d = rsqrtf(g_dis_t[n] + 1.0f);
    g_u[n] = make_float4(d * g_sum_t[n] + d * d, 1.f, 0.f, 0.f);
    g_dis_t[n] = 0.f;
    g_sum_t[n] = 0.f;
}

// ================= stream B: car chain =================
__global__ void __launch_bounds__(128, 16) k_deg_c(const int* __restrict__ eic,
                                                   const float* __restrict__ ew) {
    int t = blockIdx.x * blockDim.x + threadIdx.x;
    int base = t * 8;
    if (base >= NE) return;
    int4   ca = __ldcs((const int4*)(eic + NE + base));
    int4   cb = __ldcs((const int4*)(eic + NE + base + 4));
    float4 wa = __ldcs((const float4*)(ew + base));
    float4 wb = __ldcs((const float4*)(ew + base + 4));
    atomicAdd(&g_xd4[ca.x].w, wa.x);
    atomicAdd(&g_xd4[ca.y].w, wa.y);
    atomicAdd(&g_xd4[ca.z].w, wa.z);
    atomicAdd(&g_xd4[ca.w].w, wa.w);
    atomicAdd(&g_xd4[cb.x].w, wb.x);
    atomicAdd(&g_xd4[cb.y].w, wb.y);
    atomicAdd(&g_xd4[cb.z].w, wb.z);
    atomicAdd(&g_xd4[cb.w].w, wb.w);
}

__global__ void __launch_bounds__(128, 12) k_agg_c(const int* __restrict__ eic,
                                                   const float* __restrict__ ew) {
    int t = blockIdx.x * blockDim.x + threadIdx.x;
    int base = t * 4;
    if (base >= NE) return;
    int4   rc4 = __ldcs((const int4*)(eic + base));
    int4   cc4 = __ldcs((const int4*)(eic + NE + base));
    float4 w4  = __ldcs((const float4*)(ew + base));
    int rc[4] = {rc4.x, rc4.y, rc4.z, rc4.w};
    int cc[4] = {cc4.x, cc4.y, cc4.z, cc4.w};
    float w[4] = {w4.x, w4.y, w4.z, w4.w};
    float4 xd[4];
    #pragma unroll
    for (int k = 0; k < 4; k++) xd[k] = g_xd4[rc[k]];
    #pragma unroll
    for (int k = 0; k < 4; k++) {
        float nw = rsqrtf(xd[k].w + 1.0f) * w[k];
        red_add_v4(&g_gc4[cc[k]], nw * xd[k].x, nw * xd[k].y, nw * xd[k].z, 0.f);
    }
}

// 1 node/thread — wide grid
__global__ void __launch_bounds__(256) k_u_c() {
    int c = blockIdx.x * blockDim.x + threadIdx.x;
    if (c >= NC) return;
    float4 gc = g_gc4[c];
    float4 xd = g_xd4[c];
    float d  = rsqrtf(xd.w + 1.0f);
    float dd = d * d;
    g_u[NT + c] = make_float4(d * gc.x + dd * xd.x,
                              d * gc.y + dd * xd.y,
                              d * gc.z + dd * xd.z,
                              1.f);
    g_gc4[c] = make_float4(0.f, 0.f, 0.f, 0.f);
    ((float*)&g_xd4[c])[3] = 0.f;
}

// ================= pair scoring: 2 pairs/thread, in-block M compute =================
__global__ void __launch_bounds__(256) k_pair(const int* __restrict__ src,
                                              const int* __restrict__ dst,
                                              const float* __restrict__ Wt,
                                              const float* __restrict__ bt,
                                              const float* __restrict__ Wc,
                                              const float* __restrict__ bc,
                                              const float* __restrict__ wl,
                                              const float* __restrict__ bl,
                                              float* __restrict__ out) {
    __shared__ float B[6][HD];
    __shared__ float Bw[HD];
    __shared__ float M[36];
    {
        int h = threadIdx.x;
        if (h < HD) {
            B[0][h] = __ldg(Wt + h);
            B[1][h] = __ldg(bt + h);
            B[2][h] = __ldg(Wc + h);
            B[3][h] = __ldg(Wc + HD + h);
            B[4][h] = __ldg(Wc + 2 * HD + h);
            B[5][h] = __ldg(bc + h);
            Bw[h]   = __ldg(wl + h);
        }
        __syncthreads();
        int warp = threadIdx.x >> 5, lane = threadIdx.x & 31;
        for (int pi = warp; pi < 36; pi += 8) {
            int i = pi / 6, j = pi % 6;
            float s = 0.f;
            #pragma unroll
            for (int tt = lane; tt < HD; tt += 32)
                s += B[i][tt] * B[j][tt] * Bw[tt];
            #pragma unroll
            for (int o = 16; o > 0; o >>= 1)
                s += __shfl_xor_sync(0xffffffff, s, o);
            if (lane == 0) M[pi] = s;
        }
        __syncthreads();
    }

    int t = blockIdx.x * blockDim.x + threadIdx.x;
    int base = t * 2;
    if (base >= NP) return;
    int2 s2 = __ldcs((const int2*)(src + base));
    int2 d2 = __ldcs((const int2*)(dst + base));
    float blv = __ldg(bl);
    int ss[2] = {s2.x, s2.y};
    int dd[2] = {d2.x, d2.y};
    float4 usv[2], udv[2];
    #pragma unroll
    for (int k = 0; k < 2; k++) { usv[k] = g_u[ss[k]]; udv[k] = g_u[dd[k]]; }
    float res[2];
    #pragma unroll
    for (int k = 0; k < 2; k++) {
        float us[6] = {0.f, 0.f, 0.f, 0.f, 0.f, 0.f};
        float ud[6] = {0.f, 0.f, 0.f, 0.f, 0.f, 0.f};
        if (ss[k] < NT) { us[0] = usv[k].x; us[1] = usv[k].y; }
        else            { us[2] = usv[k].x; us[3] = usv[k].y; us[4] = usv[k].z; us[5] = usv[k].w; }
        if (dd[k] < NT) { ud[0] = udv[k].x; ud[1] = udv[k].y; }
        else            { ud[2] = udv[k].x; ud[3] = udv[k].y; ud[4] = udv[k].z; ud[5] = udv[k].w; }
        float acc = blv;
        #pragma unroll
        for (int i = 0; i < 6; i++) {
            float tt = 0.f;
            #pragma unroll
            for (int j = 0; j < 6; j++)
                tt += M[6 * i + j] * ud[j];
            acc += us[i] * tt;
        }
        res[k] = acc;
    }
    out[base] = res[0];
    out[base + 1] = res[1];
}

extern "C" void kernel_launch(void* const* d_in, const int* in_sizes, int n_in,
                              void* d_out, int out_size) {
    const float* xcar = (const float*)d_in[0];
    const int*   eit  = (const int*)d_in[1];
    const int*   eic  = (const int*)d_in[2];
    const float* ew   = (const float*)d_in[3];
    const int*   src  = (const int*)d_in[4];
    const int*   dst  = (const int*)d_in[5];
    int w0 = (in_sizes[6] == 1) ? 7 : 6;
    const float* Wt = (const float*)d_in[w0 + 0];
    const float* bt = (const float*)d_in[w0 + 1];
    const float* Wc = (const float*)d_in[w0 + 2];
    const float* bc = (const float*)d_in[w0 + 3];
    const float* wl = (const float*)d_in[w0 + 4];
    const float* bl = (const float*)d_in[w0 + 5];
    float* out = (float*)d_out;

    static cudaStream_t sB = 0;
    static cudaEvent_t eFork = 0, eDegT = 0, eUc = 0;
    if (sB == 0) {
        cudaStreamCreateWithFlags(&sB, cudaStreamNonBlocking);
        cudaEventCreateWithFlags(&eFork, cudaEventDisableTiming);
        cudaEventCreateWithFlags(&eDegT, cudaEventDisableTiming);
        cudaEventCreateWithFlags(&eUc,   cudaEventDisableTiming);
    }

    const int TPB_E = 128;  // edge kernels: fine granularity for tail balance
    const int TPB   = 256;
    const int GE8 = (NE / 8 + TPB_E - 1) / TPB_E;
    const int GE4 = (NE / 4 + TPB_E - 1) / TPB_E;

    cudaEventRecord(eFork, 0);
    cudaStreamWaitEvent(sB, eFork, 0);

    // stream A: truck chain (deg_t also packs xcar into xd4.xyz)
    k_deg_t<<<GE8, TPB_E>>>(eit, xcar);
    cudaEventRecord(eDegT, 0);
    k_agg_t<<<GE4, TPB_E>>>(eit);
    k_u_t<<<(NT + TPB - 1) / TPB, TPB>>>();

    // stream B: car chain (agg_c needs xd4.xyz packed by deg_t)
    k_deg_c<<<GE8, TPB_E, 0, sB>>>(eic, ew);
    cudaStreamWaitEvent(sB, eDegT, 0);
    k_agg_c<<<GE4, TPB_E, 0, sB>>>(eic, ew);
    k_u_c<<<(NC + TPB - 1) / TPB, TPB, 0, sB>>>();
    cudaEventRecord(eUc, sB);

    // join + score on stream A
    cudaStreamWaitEvent(0, eUc, 0);
    k_pair<<<(NP / 2 + TPB - 1) / TPB, TPB>>>(src, dst, Wt, bt, Wc, bc, wl, bl, out);
}